// round 2
// baseline (speedup 1.0000x reference)
#include <cuda_runtime.h>

#define BATCH 2
#define SEQ 384
#define HID 128
#define TABLE (2 * SEQ + 1)   // 769
#define F4H (4 * HID)         // 512

// Precomputed folded tables: T[x][t][h] = sum_f pe_x[t][f] * W[h][x*128 + f]
__device__ float g_T[4][TABLE][HID];

// ---------------------------------------------------------------------------
// Stage 1: fold the 4 PE tables through their W chunks.
// Grid: (ceil(TABLE/16), 4 tables), 256 threads.
// Each thread computes a 2t x 4h micro-tile; pe rows staged in smem,
// W chunk (64KB) streamed through L1 as float4 (fully L1-resident).
// ---------------------------------------------------------------------------
__global__ __launch_bounds__(256) void table_gemm_kernel(
    const float* __restrict__ pe0, const float* __restrict__ pe1,
    const float* __restrict__ pe2, const float* __restrict__ pe3,
    const float* __restrict__ W) {
    const int table = blockIdx.y;
    const int tbase = blockIdx.x * 16;
    const float* pe = (table == 0) ? pe0 : (table == 1) ? pe1 : (table == 2) ? pe2 : pe3;

    __shared__ float pe_s[16][HID];
    for (int idx = threadIdx.x; idx < 16 * HID; idx += 256) {
        int t = idx >> 7, f = idx & 127;
        int gt = tbase + t;
        pe_s[t][f] = (gt < TABLE) ? pe[gt * HID + f] : 0.0f;
    }
    __syncthreads();

    const int tx = threadIdx.x & 31;   // h-group
    const int ty = threadIdx.x >> 5;   // t-group (0..7)
    const int h0 = tx * 4;
    const int t0 = ty * 2;
    const int off = table * HID;

    float acc[2][4] = {};
#pragma unroll 4
    for (int f = 0; f < HID; f += 4) {
        float4 a0 = *(const float4*)&pe_s[t0][f];
        float4 a1 = *(const float4*)&pe_s[t0 + 1][f];
#pragma unroll
        for (int j = 0; j < 4; j++) {
            float4 w = *(const float4*)&W[(h0 + j) * F4H + off + f];
            acc[0][j] += a0.x * w.x + a0.y * w.y + a0.z * w.z + a0.w * w.w;
            acc[1][j] += a1.x * w.x + a1.y * w.y + a1.z * w.z + a1.w * w.w;
        }
    }

#pragma unroll
    for (int i = 0; i < 2; i++) {
        int gt = tbase + t0 + i;
        if (gt < TABLE) {
            float4 r = make_float4(acc[i][0], acc[i][1], acc[i][2], acc[i][3]);
            *(float4*)&g_T[table][gt][h0] = r;
        }
    }
}

// ---------------------------------------------------------------------------
// Stage 2: out[b,q,k,:] = relu(Tss[i_ss] + Tse[i_se] + Tes[i_es] + Tee[i_ee] + b)
// One warp per output row (128 floats); lane owns one float4.
// 4x 512B gathers (L2-resident) + 512B store per row.
// ---------------------------------------------------------------------------
__global__ __launch_bounds__(256) void fuse_kernel(
    const int* __restrict__ pos_s, const int* __restrict__ pos_e,
    const float* __restrict__ bias, float* __restrict__ out) {
    const int warp = (blockIdx.x << 3) + (threadIdx.x >> 5);
    const int lane = threadIdx.x & 31;

    const int k = warp % SEQ;
    const int bq = warp / SEQ;              // b*SEQ + q
    const int bbase = (bq / SEQ) * SEQ;     // b*SEQ

    const int aq = pos_s[bq];
    const int eq = pos_e[bq];
    const int ck = pos_s[bbase + k];
    const int dk = pos_e[bbase + k];

    const float4* __restrict__ Tss = (const float4*)g_T[0];
    const float4* __restrict__ Tse = (const float4*)g_T[1];
    const float4* __restrict__ Tes = (const float4*)g_T[2];
    const float4* __restrict__ Tee = (const float4*)g_T[3];

    const int iss = (aq - ck + SEQ) * (HID / 4) + lane;
    const int ise = (aq - dk + SEQ) * (HID / 4) + lane;
    const int ies = (eq - ck + SEQ) * (HID / 4) + lane;
    const int iee = (eq - dk + SEQ) * (HID / 4) + lane;

    float4 v0 = __ldg(Tss + iss);
    float4 v1 = __ldg(Tse + ise);
    float4 v2 = __ldg(Tes + ies);
    float4 v3 = __ldg(Tee + iee);
    float4 bb = __ldg((const float4*)bias + lane);

    float4 r;
    r.x = fmaxf(v0.x + v1.x + v2.x + v3.x + bb.x, 0.0f);
    r.y = fmaxf(v0.y + v1.y + v2.y + v3.y + bb.y, 0.0f);
    r.z = fmaxf(v0.z + v1.z + v2.z + v3.z + bb.z, 0.0f);
    r.w = fmaxf(v0.w + v1.w + v2.w + v3.w + bb.w, 0.0f);

    ((float4*)out)[warp * (HID / 4) + lane] = r;
}

extern "C" void kernel_launch(void* const* d_in, const int* in_sizes, int n_in,
                              void* d_out, int out_size) {
    const int* pos_s   = (const int*)d_in[0];
    const int* pos_e   = (const int*)d_in[1];
    const float* pe_ss = (const float*)d_in[2];
    const float* pe_se = (const float*)d_in[3];
    const float* pe_es = (const float*)d_in[4];
    const float* pe_ee = (const float*)d_in[5];
    const float* W     = (const float*)d_in[6];
    const float* bias  = (const float*)d_in[7];
    float* out = (float*)d_out;

    dim3 g1((TABLE + 15) / 16, 4);
    table_gemm_kernel<<<g1, 256>>>(pe_ss, pe_se, pe_es, pe_ee, W);

    const int rows = BATCH * SEQ * SEQ;          // 294912
    fuse_kernel<<<rows / 8, 256>>>(pos_s, pos_e, bias, out);
}

// round 3
// speedup vs baseline: 1.4234x; 1.4234x over previous
#include <cuda_runtime.h>

#define BATCH 2
#define SEQ 384
#define HID 128
#define TABLE (2 * SEQ + 1)   // 769
#define F4H (4 * HID)         // 512

// Folded per-table results: T[x][t][h] = pe_x[t] @ W_x^T  (+ bias folded into x=0)
__device__ float g_T[4][TABLE][HID];
// Fully fused table: T2[(d*8+sq)*8+sk][h] = relu(sum of 4 gathers + b). 25.2 MB.
__device__ float g_T2[TABLE * 64 * HID];

// ---------------------------------------------------------------------------
// Stage 1: T[x] = pe_x @ W_x^T, coalesced. Block = (32 t-rows, one table).
// W chunk staged to smem TRANSPOSED (w_s[f][h]) so gmem loads are f-contiguous
// and smem reads are conflict-free float4s over h.
// ---------------------------------------------------------------------------
__global__ __launch_bounds__(256) void table_gemm_kernel(
    const float* __restrict__ pe0, const float* __restrict__ pe1,
    const float* __restrict__ pe2, const float* __restrict__ pe3,
    const float* __restrict__ W, const float* __restrict__ bias) {
    const int table = blockIdx.y;
    const int tbase = blockIdx.x * 32;
    const float* pe = (table == 0) ? pe0 : (table == 1) ? pe1 : (table == 2) ? pe2 : pe3;

    __shared__ float pe_s[32][129];     // pad -> conflict-free scalar reads
    __shared__ float w_s[128][36];      // transposed, pad 36 keeps float4 align

    for (int idx = threadIdx.x; idx < 32 * HID; idx += 256) {
        int t = idx >> 7, f = idx & 127;
        int gt = tbase + t;
        pe_s[t][f] = (gt < TABLE) ? pe[gt * HID + f] : 0.0f;
    }

    const int t  = threadIdx.x >> 3;    // 0..31
    const int hg = threadIdx.x & 7;     // 0..7
    const int gt = tbase + t;

#pragma unroll
    for (int hc = 0; hc < 4; hc++) {
        __syncthreads();
        // load W rows [hc*32, hc*32+32), cols [table*128, +128), f-contiguous
        for (int idx = threadIdx.x; idx < 32 * HID; idx += 256) {
            int r = idx >> 7, f = idx & 127;
            w_s[f][r] = W[(hc * 32 + r) * F4H + table * HID + f];
        }
        __syncthreads();

        float acc0 = 0.f, acc1 = 0.f, acc2 = 0.f, acc3 = 0.f;
#pragma unroll 8
        for (int f = 0; f < HID; f++) {
            float a = pe_s[t][f];
            float4 w = *(const float4*)&w_s[f][hg * 4];
            acc0 += a * w.x; acc1 += a * w.y; acc2 += a * w.z; acc3 += a * w.w;
        }
        if (gt < TABLE) {
            int h0 = hc * 32 + hg * 4;
            if (table == 0) {
                float4 bb = *(const float4*)&bias[h0];
                acc0 += bb.x; acc1 += bb.y; acc2 += bb.z; acc3 += bb.w;
            }
            *(float4*)&g_T[table][gt][h0] = make_float4(acc0, acc1, acc2, acc3);
        }
    }
}

// ---------------------------------------------------------------------------
// Stage 1b: build the fully fused table.
// T2[d][sq][sk][:] = relu(T0[d] + T1[max(d-sk,0)] + T2[min(d+sq,768)]
//                         + T3[clamp(d+sq-sk)])   (bias already in T0)
// Clamped entries are never read by real data (valid indices stay in range).
// One warp per 128-float row.
// ---------------------------------------------------------------------------
__global__ __launch_bounds__(256) void build_kernel() {
    const int warp = (blockIdx.x << 3) + (threadIdx.x >> 5);
    const int lane = threadIdx.x & 31;

    const int d  = warp >> 6;
    const int sq = (warp >> 3) & 7;
    const int sk = warp & 7;

    const int ise = max(d - sk, 0);
    const int ies = min(d + sq, TABLE - 1);
    const int iee = min(max(d + sq - sk, 0), TABLE - 1);

    const float4* T0 = (const float4*)g_T[0];
    const float4* T1 = (const float4*)g_T[1];
    const float4* T2 = (const float4*)g_T[2];
    const float4* T3 = (const float4*)g_T[3];

    float4 v0 = __ldg(T0 + d   * 32 + lane);
    float4 v1 = __ldg(T1 + ise * 32 + lane);
    float4 v2 = __ldg(T2 + ies * 32 + lane);
    float4 v3 = __ldg(T3 + iee * 32 + lane);

    float4 r;
    r.x = fmaxf(v0.x + v1.x + v2.x + v3.x, 0.0f);
    r.y = fmaxf(v0.y + v1.y + v2.y + v3.y, 0.0f);
    r.z = fmaxf(v0.z + v1.z + v2.z + v3.z, 0.0f);
    r.w = fmaxf(v0.w + v1.w + v2.w + v3.w, 0.0f);

    ((float4*)g_T2)[warp * 32 + lane] = r;
}

// ---------------------------------------------------------------------------
// Stage 2: out[b,q,k,:] = T2row[(d,sq,sk)]. One gather + one streaming store
// per row (8 L1 wavefronts). __stcs keeps the 25MB T2 resident in L2.
// ---------------------------------------------------------------------------
__global__ __launch_bounds__(256) void fuse_kernel(
    const int* __restrict__ pos_s, const int* __restrict__ pos_e,
    float* __restrict__ out) {
    const int warp = (blockIdx.x << 3) + (threadIdx.x >> 5);
    const int lane = threadIdx.x & 31;

    const int k = warp % SEQ;
    const int bq = warp / SEQ;            // b*SEQ + q
    const int bbase = (bq / SEQ) * SEQ;   // b*SEQ

    const int aq = __ldg(pos_s + bq);
    const int eq = __ldg(pos_e + bq);
    const int ck = __ldg(pos_s + bbase + k);
    const int dk = __ldg(pos_e + bbase + k);

    const int d  = aq - ck + SEQ;
    const int sq = eq - aq;               // in [0,7]
    const int sk = dk - ck;               // in [0,7]
    const int row = (d << 6) + (sq << 3) + sk;

    float4 v = __ldg((const float4*)g_T2 + row * 32 + lane);
    __stcs((float4*)out + warp * 32 + lane, v);
}

extern "C" void kernel_launch(void* const* d_in, const int* in_sizes, int n_in,
                              void* d_out, int out_size) {
    const int* pos_s   = (const int*)d_in[0];
    const int* pos_e   = (const int*)d_in[1];
    const float* pe_ss = (const float*)d_in[2];
    const float* pe_se = (const float*)d_in[3];
    const float* pe_es = (const float*)d_in[4];
    const float* pe_ee = (const float*)d_in[5];
    const float* W     = (const float*)d_in[6];
    const float* bias  = (const float*)d_in[7];
    float* out = (float*)d_out;

    dim3 g1((TABLE + 31) / 32, 4);                 // 25 x 4
    table_gemm_kernel<<<g1, 256>>>(pe_ss, pe_se, pe_es, pe_ee, W, bias);

    build_kernel<<<(TABLE * 64) / 8, 256>>>();     // 6152 blocks

    const int rows = BATCH * SEQ * SEQ;            // 294912
    fuse_kernel<<<rows / 8, 256>>>(pos_s, pos_e, out);
}

// round 8
// speedup vs baseline: 1.5954x; 1.1208x over previous
#include <cuda_runtime.h>

#define BATCH 2
#define SEQ 384
#define HID 128
#define TABLE (2 * SEQ + 1)   // 769
#define F4H (4 * HID)         // 512

// Folded per-table results: T[x][t][h] = pe_x[t] @ W_x^T  (+ bias folded into x=0)
__device__ float g_T[4][TABLE][HID];
// Fully fused table: T2[(d*8+sq)*8+sk][h] = relu(sum of 4 gathers + b). 25.2 MB.
__device__ float g_T2[TABLE * 64 * HID];

// ---------------------------------------------------------------------------
// Stage 1: T[x] = pe_x @ W_x^T.
// Grid (97, 4): 388 blocks. Block = 8 t-rows x 128 h.
// Warp layout: warp w -> (tg = w>>2 in {0,1}, hq = w&3); lane -> (hg = l>>2,
// lt = l&3). Each lane owns 1 t-row and 4 h-cols; the w_s float4 is broadcast
// to the 4 lanes sharing hg -> 4x less physical smem traffic.
// W staged in two 32KB f-phases; accumulators persist across phases.
// ---------------------------------------------------------------------------
__global__ __launch_bounds__(256) void table_gemm_kernel(
    const float* __restrict__ pe0, const float* __restrict__ pe1,
    const float* __restrict__ pe2, const float* __restrict__ pe3,
    const float* __restrict__ W, const float* __restrict__ bias) {
    const int table = blockIdx.y;
    const int tbase = blockIdx.x * 8;
    const float* pe = (table == 0) ? pe0 : (table == 1) ? pe1 : (table == 2) ? pe2 : pe3;

    __shared__ float pe_s[8][HID];
    __shared__ float w_s[64][132];       // [f'][h], stride 132 (16B-aligned rows)

    // load pe tile (8 rows x 128 f), zero-padded past TABLE
    for (int idx = threadIdx.x; idx < 8 * HID; idx += 256) {
        int t = idx >> 7, f = idx & 127;
        int gt = tbase + t;
        pe_s[t][f] = (gt < TABLE) ? pe[gt * HID + f] : 0.0f;
    }

    const int w_id = threadIdx.x >> 5;
    const int lane = threadIdx.x & 31;
    const int tg = w_id >> 2;            // 0..1
    const int hq = w_id & 3;             // 0..3
    const int hg = lane >> 2;            // 0..7
    const int lt = lane & 3;             // 0..3
    const int t = tg * 4 + lt;           // 0..7
    const int h0 = (hq * 8 + hg) * 4;    // 0..124

    float a0 = 0.f, a1 = 0.f, a2 = 0.f, a3 = 0.f;

#pragma unroll
    for (int p = 0; p < 2; p++) {
        __syncthreads();
        // stage W[h=0..127][f = p*64 .. p*64+63] transposed into w_s[f'][h]
        for (int idx = threadIdx.x; idx < 128 * 64; idx += 256) {
            int r = idx >> 6, fp = idx & 63;
            w_s[fp][r] = W[r * F4H + table * HID + p * 64 + fp];
        }
        __syncthreads();

        const float* per = &pe_s[t][p * 64];
#pragma unroll 8
        for (int f = 0; f < 64; f++) {
            float a = per[f];
            float4 w = *(const float4*)&w_s[f][h0];
            a0 += a * w.x; a1 += a * w.y; a2 += a * w.z; a3 += a * w.w;
        }
    }

    const int gt = tbase + t;
    if (gt < TABLE) {
        if (table == 0) {
            float4 bb = *(const float4*)&bias[h0];
            a0 += bb.x; a1 += bb.y; a2 += bb.z; a3 += bb.w;
        }
        *(float4*)&g_T[table][gt][h0] = make_float4(a0, a1, a2, a3);
    }
}

// ---------------------------------------------------------------------------
// Stage 1b: fully fused table.
// T2[d][sq][sk][:] = relu(T0[d] + T1[d-sk] + T2[d+sq] + T3[d+sq-sk])
// (bias already folded into T0; clamped entries never read by real data)
// ---------------------------------------------------------------------------
__global__ __launch_bounds__(256) void build_kernel() {
    const int warp = (blockIdx.x << 3) + (threadIdx.x >> 5);
    const int lane = threadIdx.x & 31;

    const int d  = warp >> 6;
    const int sq = (warp >> 3) & 7;
    const int sk = warp & 7;

    const int ise = max(d - sk, 0);
    const int ies = min(d + sq, TABLE - 1);
    const int iee = min(max(d + sq - sk, 0), TABLE - 1);

    const float4* T0 = (const float4*)g_T[0];
    const float4* T1 = (const float4*)g_T[1];
    const float4* T2 = (const float4*)g_T[2];
    const float4* T3 = (const float4*)g_T[3];

    float4 v0 = __ldg(T0 + d   * 32 + lane);
    float4 v1 = __ldg(T1 + ise * 32 + lane);
    float4 v2 = __ldg(T2 + ies * 32 + lane);
    float4 v3 = __ldg(T3 + iee * 32 + lane);

    float4 r;
    r.x = fmaxf(v0.x + v1.x + v2.x + v3.x, 0.0f);
    r.y = fmaxf(v0.y + v1.y + v2.y + v3.y, 0.0f);
    r.z = fmaxf(v0.z + v1.z + v2.z + v3.z, 0.0f);
    r.w = fmaxf(v0.w + v1.w + v2.w + v3.w, 0.0f);

    ((float4*)g_T2)[warp * 32 + lane] = r;
}

// ---------------------------------------------------------------------------
// Stage 2: out[b,q,k,:] = T2row[(d,sq,sk)]. One L2-resident gather + one
// streaming (evict-first) store per 512B row.
// ---------------------------------------------------------------------------
__global__ __launch_bounds__(256) void fuse_kernel(
    const int* __restrict__ pos_s, const int* __restrict__ pos_e,
    float* __restrict__ out) {
    const int warp = (blockIdx.x << 3) + (threadIdx.x >> 5);
    const int lane = threadIdx.x & 31;

    const int k = warp % SEQ;
    const int bq = warp / SEQ;            // b*SEQ + q
    const int bbase = (bq / SEQ) * SEQ;   // b*SEQ

    const int aq = __ldg(pos_s + bq);
    const int eq = __ldg(pos_e + bq);
    const int ck = __ldg(pos_s + bbase + k);
    const int dk = __ldg(pos_e + bbase + k);

    const int d  = aq - ck + SEQ;
    const int sq = eq - aq;               // in [0,7]
    const int sk = dk - ck;               // in [0,7]
    const int row = (d << 6) + (sq << 3) + sk;

    float4 v = __ldg((const float4*)g_T2 + row * 32 + lane);
    __stcs((float4*)out + warp * 32 + lane, v);
}

extern "C" void kernel_launch(void* const* d_in, const int* in_sizes, int n_in,
                              void* d_out, int out_size) {
    const int* pos_s   = (const int*)d_in[0];
    const int* pos_e   = (const int*)d_in[1];
    const float* pe_ss = (const float*)d_in[2];
    const float* pe_se = (const float*)d_in[3];
    const float* pe_es = (const float*)d_in[4];
    const float* pe_ee = (const float*)d_in[5];
    const float* W     = (const float*)d_in[6];
    const float* bias  = (const float*)d_in[7];
    float* out = (float*)d_out;

    dim3 g1((TABLE + 7) / 8, 4);                   // 97 x 4 = 388 blocks
    table_gemm_kernel<<<g1, 256>>>(pe_ss, pe_se, pe_es, pe_ee, W, bias);

    build_kernel<<<(TABLE * 64) / 8, 256>>>();     // 6152 blocks

    const int rows = BATCH * SEQ * SEQ;            // 294912
    fuse_kernel<<<rows / 8, 256>>>(pos_s, pos_e, out);
}